// round 2
// baseline (speedup 1.0000x reference)
#include <cuda_runtime.h>
#include <math.h>

#define IGNORE_LABEL (-100LL)
#define MAXB 64

// scratch (device globals; no allocation allowed)
__device__ double g_tasksum[MAXB];
__device__ int    g_correct[MAXB];
__device__ int    g_valid[MAXB];
__device__ int    g_labels_is64;

__global__ void init_kernel(int nb, const void* __restrict__ labels,
                            int rows, int V) {
    int i = threadIdx.x;
    if (i < nb) { g_tasksum[i] = 0.0; g_correct[i] = 0; g_valid[i] = 0; }
    if (i == 0) {
        // Probe labels dtype: read first rows/2 values as int64.
        // rows/2 * 8B == rows * 4B, so this is in-bounds for either dtype.
        const long long* p64 = (const long long*)labels;
        int ok = 1;
        int n = rows >> 1;
        for (int k = 0; k < n; k++) {
            long long v = p64[k];
            if (!((v >= 0 && v < (long long)V) || v == IGNORE_LABEL)) { ok = 0; break; }
        }
        g_labels_is64 = ok;
    }
}

// one block per token row
__global__ void row_kernel(const float* __restrict__ logits,
                           const void* __restrict__ labels_raw,
                           int V, int Lseq) {
    const int row = blockIdx.x;
    const int tid = threadIdx.x;
    const int nt  = blockDim.x;
    const float* __restrict__ x = logits + (size_t)row * V;

    long long label;
    if (g_labels_is64) label = ((const long long*)labels_raw)[row];
    else               label = (long long)((const int*)labels_raw)[row];

    float lsum = 0.f;
    float lmax = -INFINITY;
    int   lidx = 0x7fffffff;

    const int V4 = V >> 2;                       // V=32000 -> 8000
    const float4* __restrict__ x4 = (const float4*)x;
    for (int i = tid; i < V4; i += nt) {
        float4 v = __ldg(&x4[i]);
        int base = i << 2;
        float s0 = v.x < 0.f ? 1.f / (1.f - v.x) : v.x + 1.f;
        float s1 = v.y < 0.f ? 1.f / (1.f - v.y) : v.y + 1.f;
        float s2 = v.z < 0.f ? 1.f / (1.f - v.z) : v.z + 1.f;
        float s3 = v.w < 0.f ? 1.f / (1.f - v.w) : v.w + 1.f;
        lsum += (s0 + s1) + (s2 + s3);
        // argmax with first-index tie-break (visit order is increasing idx per thread)
        if (v.x > lmax || (v.x == lmax && base + 0 < lidx)) { lmax = v.x; lidx = base + 0; }
        if (v.y > lmax || (v.y == lmax && base + 1 < lidx)) { lmax = v.y; lidx = base + 1; }
        if (v.z > lmax || (v.z == lmax && base + 2 < lidx)) { lmax = v.z; lidx = base + 2; }
        if (v.w > lmax || (v.w == lmax && base + 3 < lidx)) { lmax = v.w; lidx = base + 3; }
    }
    // tail (V not multiple of 4)
    for (int i = (V4 << 2) + tid; i < V; i += nt) {
        float v = __ldg(&x[i]);
        float s = v < 0.f ? 1.f / (1.f - v) : v + 1.f;
        lsum += s;
        if (v > lmax || (v == lmax && i < lidx)) { lmax = v; lidx = i; }
    }

    __shared__ double ssum[256];
    __shared__ float  smax[256];
    __shared__ int    sidx[256];
    ssum[tid] = (double)lsum;
    smax[tid] = lmax;
    sidx[tid] = lidx;
    __syncthreads();
    for (int s = nt >> 1; s > 0; s >>= 1) {
        if (tid < s) {
            ssum[tid] += ssum[tid + s];
            float mv = smax[tid + s]; int mi = sidx[tid + s];
            if (mv > smax[tid] || (mv == smax[tid] && mi < sidx[tid])) {
                smax[tid] = mv; sidx[tid] = mi;
            }
        }
        __syncthreads();
    }

    if (tid == 0) {
        int b = row / Lseq;
        if (label >= 0 && label < (long long)V) {   // valid label only (OOB-safe)
            double xl = (double)x[(int)label];
            double sl = xl < 0.0 ? 1.0 / (1.0 - xl + 1e-30) : xl + 1.0;
            double pt = log(ssum[0]) - log(sl);   // -log(s_label / sum)
            atomicAdd(&g_tasksum[b], pt);
            atomicAdd(&g_valid[b], 1);
            if ((long long)sidx[0] == label) atomicAdd(&g_correct[b], 1);
        }
    }
}

__global__ void final_kernel(const float* __restrict__ qh,
                             const float* __restrict__ qc,
                             float* __restrict__ out, int Bn) {
    if (threadIdx.x == 0 && blockIdx.x == 0) {
        float Ltask = 0.f;
        float lh = 0.f, lc = 0.f;
        for (int b = 0; b < Bn; b++) {
            float cnt = (float)(g_valid[b] > 1 ? g_valid[b] : 1);
            Ltask += (float)g_tasksum[b] / cnt;
            // seq correct iff every valid token predicted correctly
            float t = (g_correct[b] == g_valid[b]) ? 1.f : 0.f;
            float xh = qh[b];
            lh += fmaxf(xh, 0.f) - xh * t + log1pf(expf(-fabsf(xh)));
            float tc = 1.f / (1.f + expf(-xh));   // sigmoid(stop_grad(q_halt))
            float xc = qc[b];
            lc += fmaxf(xc, 0.f) - xc * tc + log1pf(expf(-fabsf(xc)));
        }
        Ltask /= (float)Bn;
        float Lhalt = 0.5f * (lh / (float)Bn + lc / (float)Bn);
        out[0] = Ltask + Lhalt;
    }
}

extern "C" void kernel_launch(void* const* d_in, const int* in_sizes, int n_in,
                              void* d_out, int out_size) {
    // Identify inputs by size, not position:
    //   logits  : largest buffer (B*L*V)
    //   labels  : second-largest (B*L)
    //   qh, qc  : the two size-B buffers, in original relative order
    int li = 0;
    for (int i = 1; i < n_in; i++) if (in_sizes[i] > in_sizes[li]) li = i;
    int lab = -1;
    for (int i = 0; i < n_in; i++) {
        if (i == li) continue;
        if (lab < 0 || in_sizes[i] > in_sizes[lab]) lab = i;
    }
    int qi[2]; int nq = 0;
    for (int i = 0; i < n_in && nq < 2; i++) {
        if (i != li && i != lab) qi[nq++] = i;
    }

    const float* logits = (const float*)d_in[li];
    const void*  labels = d_in[lab];
    const float* qh     = (const float*)d_in[qi[0]];
    const float* qc     = (const float*)d_in[qi[1]];

    const int Bn   = in_sizes[qi[0]];            // 4
    const int rows = in_sizes[lab];              // B*L = 4096
    const int Lseq = rows / Bn;                  // 1024
    const int V    = (int)((long long)in_sizes[li] / rows);  // 32000

    init_kernel<<<1, 64>>>(Bn, labels, rows, V);
    row_kernel<<<rows, 256>>>(logits, labels, V, Lseq);
    final_kernel<<<1, 32>>>(qh, qc, (float*)d_out, Bn);
}

// round 3
// speedup vs baseline: 1.6454x; 1.6454x over previous
#include <cuda_runtime.h>
#include <math.h>

#define IGNORE_LABEL (-100LL)
#define MAXB 64

__device__ double g_tasksum[MAXB];
__device__ int    g_correct[MAXB];
__device__ int    g_valid[MAXB];
__device__ int    g_labels_is64;

__device__ __forceinline__ float frcp_fast(float t) {
    float r;
    asm("rcp.approx.ftz.f32 %0, %1;" : "=f"(r) : "f"(t));
    return r;
}

__device__ __forceinline__ float smap(float v) {
    // s(x) = x<0 ? 1/(1-x) : x+1   (eps irrelevant at fp32 scale)
    float r = frcp_fast(1.0f - v);
    return v < 0.0f ? r : v + 1.0f;
}

__global__ void init_kernel(int nb, const void* __restrict__ labels,
                            int rows, int V) {
    __shared__ int bad;
    int tid = threadIdx.x;
    if (tid == 0) bad = 0;
    if (tid < nb) { g_tasksum[tid] = 0.0; g_correct[tid] = 0; g_valid[tid] = 0; }
    __syncthreads();
    // Probe labels dtype: interpret first rows/2 entries as int64.
    // rows/2 * 8B == rows * 4B, in-bounds under either dtype.
    const long long* p64 = (const long long*)labels;
    int n = rows >> 1;
    int viol = 0;
    for (int k = tid; k < n; k += blockDim.x) {
        long long v = p64[k];
        if (!((v >= 0 && v < (long long)V) || v == IGNORE_LABEL)) viol = 1;
    }
    if (viol) atomicOr(&bad, 1);
    __syncthreads();
    if (tid == 0) g_labels_is64 = !bad;
}

// one block per token row
__global__ void __launch_bounds__(256) row_kernel(
        const float* __restrict__ logits,
        const void* __restrict__ labels_raw,
        int V, int Lseq) {
    const int row = blockIdx.x;
    const int tid = threadIdx.x;
    const int nt  = blockDim.x;
    const float* __restrict__ x = logits + (size_t)row * V;

    long long label;
    if (g_labels_is64) label = ((const long long*)labels_raw)[row];
    else               label = (long long)((const int*)labels_raw)[row];

    float sumA = 0.f, sumB = 0.f;
    float lmax = -INFINITY;
    int   lidx = 0x7fffffff;

    const int V4 = V >> 2;
    const float4* __restrict__ x4 = (const float4*)x;
    #pragma unroll 4
    for (int i = tid; i < V4; i += nt) {
        float4 v = __ldg(&x4[i]);
        int base = i << 2;
        float s0 = smap(v.x);
        float s1 = smap(v.y);
        float s2 = smap(v.z);
        float s3 = smap(v.w);
        sumA += s0 + s1;
        sumB += s2 + s3;
        // strict > : keeps first (smallest) index within this thread,
        // since per-thread visit order is strictly increasing index.
        if (v.x > lmax) { lmax = v.x; lidx = base + 0; }
        if (v.y > lmax) { lmax = v.y; lidx = base + 1; }
        if (v.z > lmax) { lmax = v.z; lidx = base + 2; }
        if (v.w > lmax) { lmax = v.w; lidx = base + 3; }
    }
    // tail (V not multiple of 4)
    for (int i = (V4 << 2) + tid; i < V; i += nt) {
        float v = __ldg(&x[i]);
        sumA += smap(v);
        if (v > lmax) { lmax = v; lidx = i; }
    }

    __shared__ float  ssum[256];
    __shared__ float  smax[256];
    __shared__ int    sidx[256];
    ssum[tid] = sumA + sumB;
    smax[tid] = lmax;
    sidx[tid] = lidx;
    __syncthreads();
    for (int s = nt >> 1; s > 0; s >>= 1) {
        if (tid < s) {
            ssum[tid] += ssum[tid + s];
            float mv = smax[tid + s]; int mi = sidx[tid + s];
            // tie-break: min index on exact equality
            if (mv > smax[tid] || (mv == smax[tid] && mi < sidx[tid])) {
                smax[tid] = mv; sidx[tid] = mi;
            }
        }
        __syncthreads();
    }

    if (tid == 0) {
        int b = row / Lseq;
        if (label >= 0 && label < (long long)V) {
            double xl = (double)x[(int)label];
            double sl = xl < 0.0 ? 1.0 / (1.0 - xl + 1e-30) : xl + 1.0;
            double pt = log((double)ssum[0]) - log(sl);   // -log(s_label / sum)
            atomicAdd(&g_tasksum[b], pt);
            atomicAdd(&g_valid[b], 1);
            if ((long long)sidx[0] == label) atomicAdd(&g_correct[b], 1);
        }
    }
}

__global__ void final_kernel(const float* __restrict__ qh,
                             const float* __restrict__ qc,
                             float* __restrict__ out, int Bn) {
    if (threadIdx.x == 0 && blockIdx.x == 0) {
        float Ltask = 0.f;
        float lh = 0.f, lc = 0.f;
        for (int b = 0; b < Bn; b++) {
            float cnt = (float)(g_valid[b] > 1 ? g_valid[b] : 1);
            Ltask += (float)g_tasksum[b] / cnt;
            float t = (g_correct[b] == g_valid[b]) ? 1.f : 0.f;
            float xh = qh[b];
            lh += fmaxf(xh, 0.f) - xh * t + log1pf(expf(-fabsf(xh)));
            float tc = 1.f / (1.f + expf(-xh));
            float xc = qc[b];
            lc += fmaxf(xc, 0.f) - xc * tc + log1pf(expf(-fabsf(xc)));
        }
        Ltask /= (float)Bn;
        float Lhalt = 0.5f * (lh / (float)Bn + lc / (float)Bn);
        out[0] = Ltask + Lhalt;
    }
}

extern "C" void kernel_launch(void* const* d_in, const int* in_sizes, int n_in,
                              void* d_out, int out_size) {
    // Identify inputs by size, not position.
    int li = 0;
    for (int i = 1; i < n_in; i++) if (in_sizes[i] > in_sizes[li]) li = i;
    int lab = -1;
    for (int i = 0; i < n_in; i++) {
        if (i == li) continue;
        if (lab < 0 || in_sizes[i] > in_sizes[lab]) lab = i;
    }
    int qi[2]; int nq = 0;
    for (int i = 0; i < n_in && nq < 2; i++) {
        if (i != li && i != lab) qi[nq++] = i;
    }

    const float* logits = (const float*)d_in[li];
    const void*  labels = d_in[lab];
    const float* qh     = (const float*)d_in[qi[0]];
    const float* qc     = (const float*)d_in[qi[1]];

    const int Bn   = in_sizes[qi[0]];
    const int rows = in_sizes[lab];
    const int Lseq = rows / Bn;
    const int V    = (int)((long long)in_sizes[li] / rows);

    init_kernel<<<1, 256>>>(Bn, labels, rows, V);
    row_kernel<<<rows, 256>>>(logits, labels, V, Lseq);
    final_kernel<<<1, 32>>>(qh, qc, (float*)d_out, Bn);
}